// round 9
// baseline (speedup 1.0000x reference)
#include <cuda_runtime.h>
#include <cuda_bf16.h>
#include <cstdint>

#define B_   8192
#define T_   16
#define K_   512
#define D_   128
#define NZQ  (B_*T_*D_)      // 16777216
#define NTOK (B_*T_)         // 131072
#define EPS  5e-4f
#define FINF 3.4e38f

// ---------------- device globals (no allocs allowed) ----------------
__device__ __nv_bfloat16 g_cbh[T_*K_*D_];   // 2MB codebook bf16 (hi only)
__device__ float         g_cnorm[T_*K_];
__device__ int           g_tokens[NTOK];
__device__ unsigned char g_used[T_*K_];
__device__ float         g_partial2[NTOK/8];
__device__ int           g_amb[NTOK];
__device__ int           g_amb_count;

// ---------------- PTX helpers (base compute_103 legal) ----------------
__device__ __forceinline__ uint32_t smem_to_u32(const void* p) {
    uint32_t a;
    asm("{ .reg .u64 t; cvta.to.shared.u64 t, %1; cvt.u32.u64 %0, t; }" : "=r"(a) : "l"(p));
    return a;
}
__device__ __forceinline__ void ldsm4(uint32_t* r, uint32_t addr) {
    asm volatile("ldmatrix.sync.aligned.m8n8.x4.shared.b16 {%0,%1,%2,%3}, [%4];"
                 : "=r"(r[0]), "=r"(r[1]), "=r"(r[2]), "=r"(r[3]) : "r"(addr));
}
__device__ __forceinline__ void mma16816(float* d, const uint32_t* a, const uint32_t* b) {
    asm volatile("mma.sync.aligned.m16n8k16.row.col.f32.bf16.bf16.f32 "
                 "{%0,%1,%2,%3}, {%4,%5,%6,%7}, {%8,%9}, {%0,%1,%2,%3};"
                 : "+f"(d[0]), "+f"(d[1]), "+f"(d[2]), "+f"(d[3])
                 : "r"(a[0]), "r"(a[1]), "r"(a[2]), "r"(a[3]), "r"(b[0]), "r"(b[1]));
}
__device__ __forceinline__ void cpasync16(uint32_t smem_dst, const void* gsrc) {
    asm volatile("cp.async.cg.shared.global [%0], [%1], 16;"
                 :: "r"(smem_dst), "l"(gsrc) : "memory");
}
#define CP_COMMIT() asm volatile("cp.async.commit_group;" ::: "memory")
#define CP_WAIT(n)  asm volatile("cp.async.wait_group %0;" :: "n"(n) : "memory")

// (m1,k1,m2) merge with lowest-index tie-break
__device__ __forceinline__ void tmerge(float& m1, int& k1, float& m2,
                                       float vm1, int vk1, float vm2) {
    if (vm1 < m1 || (vm1 == m1 && vk1 < k1)) {
        m2 = fminf(m1, vm2); m1 = vm1; k1 = vk1;
    } else {
        m2 = fminf(m2, vm1);
    }
}

struct alignas(16) BH8 { __nv_bfloat16 v[8]; };
struct alignas(8)  BH4 { __nv_bfloat16 v[4]; };

// ---------------- k_prep: codebook norms + bf16 round + clears ----------------
__global__ void k_prep(const float* __restrict__ cb) {
    int gt = blockIdx.x * blockDim.x + threadIdx.x;
    int w = gt >> 5, lane = gt & 31;                  // one warp per (t,k) row
    const float4* row = (const float4*)(cb + (size_t)w * D_);
    float4 v = row[lane];
    BH4 h;
    h.v[0] = __float2bfloat16_rn(v.x);
    h.v[1] = __float2bfloat16_rn(v.y);
    h.v[2] = __float2bfloat16_rn(v.z);
    h.v[3] = __float2bfloat16_rn(v.w);
    *(uint2*)(g_cbh + (size_t)w * D_ + lane * 4) = *(uint2*)&h;
    float s = v.x*v.x + v.y*v.y + v.z*v.z + v.w*v.w;
    #pragma unroll
    for (int o = 16; o; o >>= 1) s += __shfl_xor_sync(0xffffffffu, s, o);
    if (lane == 0) { g_cnorm[w] = s; g_used[w] = 0; }
    if (gt == 0) g_amb_count = 0;
}

// ---------------- k_mma: 2-GEMM split (zh+zl)*ch + argmin, cp.async pipelined B ----------------
#define LDB   272
#define OFF_CN   0
#define OFF_AH   2048
#define OFF_AL   (OFF_AH + 128*LDB)
#define OFF_B0   (OFF_AL + 128*LDB)
#define OFF_B1   (OFF_B0 + 128*LDB)
#define OFF_RM1  (OFF_B1 + 128*LDB)
#define OFF_RM2  (OFF_RM1 + 128*2*4)
#define OFF_RK1  (OFF_RM2 + 128*2*4)
#define SMEM_MMA (OFF_RK1 + 128*2*4)    // 144384

__global__ void __launch_bounds__(256, 1) k_mma(const float* __restrict__ ze) {
    extern __shared__ char sm[];
    const uint32_t smem_base = smem_to_u32(sm);
    float* cn_s   = (float*)(sm + OFF_CN);
    float* red_m1 = (float*)(sm + OFF_RM1);
    float* red_m2 = (float*)(sm + OFF_RM2);
    int*   red_k1 = (int*)  (sm + OFF_RK1);

    const int tid = threadIdx.x, wid = tid >> 5, l = tid & 31;
    const int wm = wid >> 1, wn = wid & 1;            // 4 x 2 warp grid
    const int bx = blockIdx.x, t = blockIdx.y;

    const char* cb_base = (const char*)(g_cbh + ((size_t)(t * K_)) * D_);

    // prologue: issue B chunk 0 (128 codes x 128 d bf16 = 32KB) via cp.async
    {
        int n = tid >> 4, seg = tid & 15;   // 256 threads cover 16 rows per pass
        #pragma unroll
        for (int rr = 0; rr < 8; rr++) {
            int row = n + rr * 16;
            cpasync16(smem_base + OFF_B0 + row * LDB + seg * 16,
                      cb_base + (size_t)row * 256 + seg * 16);
        }
        CP_COMMIT();
    }

    // stage codebook norms
    for (int i = tid; i < K_; i += 256) cn_s[i] = g_cnorm[t * K_ + i];

    // A tile: 128 z-rows fp32 -> (zh, zl) bf16 padded rows
    const float* zbase = ze + ((size_t)(bx * 128) * T_ + t) * D_;
    for (int G = tid; G < 2048; G += 256) {
        int m = G >> 4, seg = G & 15;
        const float4* p = (const float4*)(zbase + (size_t)m * (T_ * D_) + seg * 8);
        float4 a = p[0], b = p[1];
        float zf[8] = {a.x, a.y, a.z, a.w, b.x, b.y, b.z, b.w};
        BH8 h, lo;
        #pragma unroll
        for (int i = 0; i < 8; i++) {
            h.v[i]  = __float2bfloat16_rn(zf[i]);
            lo.v[i] = __float2bfloat16_rn(zf[i] - __bfloat162float(h.v[i]));
        }
        *(uint4*)(sm + OFF_AH + m * LDB + seg * 16) = *(uint4*)&h;
        *(uint4*)(sm + OFF_AL + m * LDB + seg * 16) = *(uint4*)&lo;
    }

    // running per-row argmin state (thread tid < 128 owns local row = tid)
    float run_m1 = FINF, run_m2 = FINF; int run_k1 = 0;

    // LDSM base addresses (layouts validated in R7)
    const uint32_t aAddrH = smem_base + OFF_AH + (wm*32 + (l & 15)) * LDB + ((l >> 4) * 8) * 2;
    const uint32_t aAddrL = aAddrH + (OFF_AL - OFF_AH);
    const int nofs = (l & 7) + ((l >> 4) & 1) * 8;
    const int kofs = ((l >> 3) & 1) * 8;
    const uint32_t bAddr0 = smem_base + OFF_B0 + (wn*64 + nofs) * LDB + kofs * 2;
    const uint32_t bAddr1 = bAddr0 + (OFF_B1 - OFF_B0);

    for (int c = 0; c < 4; c++) {
        if (c < 3) {                                  // issue next B chunk into other buffer
            const char* src = cb_base + (size_t)(c + 1) * 128 * 256;
            uint32_t dst = smem_base + (((c + 1) & 1) ? OFF_B1 : OFF_B0);
            int n = tid >> 4, seg = tid & 15;
            #pragma unroll
            for (int rr = 0; rr < 8; rr++) {
                int row = n + rr * 16;
                cpasync16(dst + row * LDB + seg * 16, src + (size_t)row * 256 + seg * 16);
            }
            CP_COMMIT();
            CP_WAIT(1);                               // chunk c resident
        } else {
            CP_WAIT(0);
        }
        __syncthreads();   // chunk c visible to all; prev epilogue sync protects buffer reuse

        const uint32_t bA = (c & 1) ? bAddr1 : bAddr0;

        float acc[2][8][4];
        #pragma unroll
        for (int mi = 0; mi < 2; mi++)
            #pragma unroll
            for (int ni = 0; ni < 8; ni++)
                #pragma unroll
                for (int j = 0; j < 4; j++) acc[mi][ni][j] = 0.f;

        #pragma unroll 1
        for (int ks = 0; ks < 8; ks++) {
            uint32_t aH[2][4], aL[2][4], bH[4][4];
            ldsm4(aH[0], aAddrH + ks * 32);
            ldsm4(aH[1], aAddrH + 16 * LDB + ks * 32);
            ldsm4(aL[0], aAddrL + ks * 32);
            ldsm4(aL[1], aAddrL + 16 * LDB + ks * 32);
            #pragma unroll
            for (int p = 0; p < 4; p++) ldsm4(bH[p], bA + p * 16 * LDB + ks * 32);
            #pragma unroll
            for (int mi = 0; mi < 2; mi++)
                #pragma unroll
                for (int p = 0; p < 4; p++) {
                    mma16816(acc[mi][2*p],   aH[mi], &bH[p][0]);   // zh.ch
                    mma16816(acc[mi][2*p+1], aH[mi], &bH[p][2]);
                    mma16816(acc[mi][2*p],   aL[mi], &bH[p][0]);   // zl.ch
                    mma16816(acc[mi][2*p+1], aL[mi], &bH[p][2]);
                }
        }

        // per-chunk argmin epilogue: v = cn[k] - 2*s
        const int g = l >> 2, q = l & 3;
        #pragma unroll
        for (int mi = 0; mi < 2; mi++) {
            #pragma unroll
            for (int half = 0; half < 2; half++) {
                float m1 = FINF, m2 = FINF; int k1 = 0;
                #pragma unroll
                for (int ni = 0; ni < 8; ni++) {
                    #pragma unroll
                    for (int j = 0; j < 2; j++) {
                        int k = c*128 + wn*64 + ni*8 + 2*q + j;
                        float v = fmaf(-2.f, acc[mi][ni][half*2 + j], cn_s[k]);
                        if (v < m1)      { m2 = m1; m1 = v; k1 = k; }
                        else if (v < m2) { m2 = v; }
                    }
                }
                #pragma unroll
                for (int o = 1; o <= 2; o <<= 1) {    // merge across the 4 lanes of a row
                    float om1 = __shfl_xor_sync(0xffffffffu, m1, o);
                    int   ok1 = __shfl_xor_sync(0xffffffffu, k1, o);
                    float om2 = __shfl_xor_sync(0xffffffffu, m2, o);
                    tmerge(m1, k1, m2, om1, ok1, om2);
                }
                if (q == 0) {
                    int rowl = wm*32 + mi*16 + half*8 + g;
                    red_m1[rowl*2 + wn] = m1;
                    red_m2[rowl*2 + wn] = m2;
                    red_k1[rowl*2 + wn] = k1;
                }
            }
        }
        __syncthreads();   // red ready + all LDSM of this chunk done (buffer reusable)
        if (tid < 128) {
            tmerge(run_m1, run_k1, run_m2, red_m1[tid*2+0], red_k1[tid*2+0], red_m2[tid*2+0]);
            tmerge(run_m1, run_k1, run_m2, red_m1[tid*2+1], red_k1[tid*2+1], red_m2[tid*2+1]);
        }
    }

    if (tid < 128) {
        int row = (bx * 128 + tid) * T_ + t;
        g_tokens[row] = run_k1;
        if (run_m2 - run_m1 < EPS) {
            int idx = atomicAdd(&g_amb_count, 1);
            g_amb[idx] = row;
        }
    }
}

// ---------------- k_fix: exact fp32 rescan of ambiguous rows (reference formula) ----------------
__global__ void __launch_bounds__(256) k_fix(const float* __restrict__ ze,
                                             const float* __restrict__ cb) {
    __shared__ float zb[8][128];
    const int wid = threadIdx.x >> 5, lane = threadIdx.x & 31;
    const int gw = blockIdx.x * 8 + wid;
    const int nw = gridDim.x * 8;
    const int cnt = g_amb_count;
    for (int i = gw; i < cnt; i += nw) {
        int row = g_amb[i];
        int t = row & (T_ - 1);
        const float4* z4 = (const float4*)(ze + (size_t)row * D_);
        float4 zv = z4[lane];
        ((float4*)zb[wid])[lane] = zv;
        float zn = fmaf(zv.w, zv.w, fmaf(zv.z, zv.z, fmaf(zv.y, zv.y, zv.x * zv.x)));
        #pragma unroll
        for (int o = 16; o; o >>= 1) zn += __shfl_xor_sync(0xffffffffu, zn, o);
        __syncwarp();

        float bv = FINF; int bi = 0;
        for (int j = 0; j < 16; j++) {
            int k = j * 32 + lane;
            const float4* crow = (const float4*)(cb + ((size_t)(t * K_ + k)) * D_);
            float s = 0.f;
            #pragma unroll 8
            for (int d4 = 0; d4 < 32; d4++) {        // strict in-order fp32 chain
                float4 cv = crow[d4];
                s = fmaf(zb[wid][4*d4 + 0], cv.x, s);
                s = fmaf(zb[wid][4*d4 + 1], cv.y, s);
                s = fmaf(zb[wid][4*d4 + 2], cv.z, s);
                s = fmaf(zb[wid][4*d4 + 3], cv.w, s);
            }
            float v = (zn - 2.f * s) + g_cnorm[t * K_ + k];   // reference rounding order
            if (v < bv) { bv = v; bi = k; }
        }
        #pragma unroll
        for (int o = 16; o; o >>= 1) {               // lowest-index tie-break
            float ov = __shfl_xor_sync(0xffffffffu, bv, o);
            int   oi = __shfl_xor_sync(0xffffffffu, bi, o);
            if (ov < bv || (ov == bv && oi < bi)) { bv = ov; bi = oi; }
        }
        if (lane == 0) g_tokens[row] = bi;
        __syncwarp();
    }
}

// ---------------- k_copy: z_q_st + tokens + used + exact loss partials ----------------
__global__ void k_copy(const float* __restrict__ ze, const float* __restrict__ cb,
                       float* __restrict__ out) {
    __shared__ float ls[8];
    const int wid = threadIdx.x >> 5, lane = threadIdx.x & 31;
    const int row = blockIdx.x * 8 + wid;
    const int t = row & (T_ - 1);
    const int tok = g_tokens[row];
    const float4* cs = (const float4*)(cb + ((size_t)(t * K_ + tok)) * D_);
    const float4* zs = (const float4*)(ze + (size_t)row * D_);
    float4 c = cs[lane], z = zs[lane];
    float4 o;
    o.x = z.x + (c.x - z.x); o.y = z.y + (c.y - z.y);
    o.z = z.z + (c.z - z.z); o.w = z.w + (c.w - z.w);
    ((float4*)(out + (size_t)row * D_))[lane] = o;
    float dx = z.x - c.x, dy = z.y - c.y, dz = z.z - c.z, dw = z.w - c.w;
    float q = fmaf(dw, dw, fmaf(dz, dz, fmaf(dy, dy, dx * dx)));
    #pragma unroll
    for (int of = 16; of; of >>= 1) q += __shfl_xor_sync(0xffffffffu, q, of);
    if (lane == 0) {
        out[NZQ + row] = (float)tok;
        g_used[t * K_ + tok] = 1;
        ls[wid] = q;
    }
    __syncthreads();
    if (threadIdx.x == 0) {
        float s = 0.f;
        #pragma unroll
        for (int i = 0; i < 8; i++) s += ls[i];
        g_partial2[blockIdx.x] = s;
    }
}

// ---------------- k_final: scalars (1024 threads, vectorized) ----------------
__global__ void __launch_bounds__(1024) k_final(float* __restrict__ out) {
    __shared__ double ds[1024];
    __shared__ int    dc[1024];
    const int tid = threadIdx.x;
    double s = 0.0;
    const float4* p4 = (const float4*)g_partial2;     // 16384 floats = 4096 float4
    for (int i = tid; i < 4096; i += 1024) {
        float4 v = p4[i];
        s += (double)((v.x + v.y) + (v.z + v.w));
    }
    int c = 0;
    const uint2* u2 = (const uint2*)g_used;           // 8192 bytes = 1024 uint2
    {
        uint2 v = u2[tid];
        uint32_t m = v.x + v.y;                       // bytes are 0/1; no carry at <=8 per byte? sums per byte<=2 -> safe
        m = (m & 0x00FF00FFu) + ((m >> 8) & 0x00FF00FFu);
        c = (int)((m & 0xFFFFu) + (m >> 16));
    }
    ds[tid] = s; dc[tid] = c;
    __syncthreads();
    for (int st = 512; st; st >>= 1) {
        if (tid < st) { ds[tid] += ds[tid + st]; dc[tid] += dc[tid + st]; }
        __syncthreads();
    }
    if (tid == 0) {
        out[NZQ + NTOK + 0] = (float)(0.25 * ds[0] / (double)NZQ);
        out[NZQ + NTOK + 1] = (float)dc[0] / (float)(T_ * K_);
    }
}

extern "C" void kernel_launch(void* const* d_in, const int* in_sizes, int n_in,
                              void* d_out, int out_size) {
    const float* ze = (const float*)d_in[0];
    const float* cb = (const float*)d_in[1];
    float* out = (float*)d_out;

    cudaFuncSetAttribute(k_mma, cudaFuncAttributeMaxDynamicSharedMemorySize, SMEM_MMA);

    k_prep<<<1024, 256>>>(cb);
    dim3 gm(B_ / 128, T_);
    k_mma<<<gm, 256, SMEM_MMA>>>(ze);
    k_fix<<<256, 256>>>(ze, cb);
    k_copy<<<NTOK / 8, 256>>>(ze, cb, out);
    k_final<<<1, 1024>>>(out);
}

// round 10
// speedup vs baseline: 1.1706x; 1.1706x over previous
#include <cuda_runtime.h>
#include <cuda_bf16.h>
#include <cstdint>

#define B_   8192
#define T_   16
#define K_   512
#define D_   128
#define NZQ  (B_*T_*D_)      // 16777216
#define NTOK (B_*T_)         // 131072
#define EPS  5e-4f
#define FINF 3.4e38f

// ---------------- device globals (no allocs allowed) ----------------
__device__ __nv_bfloat16 g_cbh[T_*K_*D_];   // 2MB codebook bf16 (hi only)
__device__ float         g_cnorm[T_*K_];
__device__ int           g_tokens[NTOK];
__device__ unsigned char g_used[T_*K_];
__device__ float         g_partial2[NTOK/8];
__device__ int           g_amb[NTOK];
__device__ int           g_amb_count;

// ---------------- PTX helpers (base compute_103 legal) ----------------
__device__ __forceinline__ uint32_t smem_to_u32(const void* p) {
    uint32_t a;
    asm("{ .reg .u64 t; cvta.to.shared.u64 t, %1; cvt.u32.u64 %0, t; }" : "=r"(a) : "l"(p));
    return a;
}
__device__ __forceinline__ void ldsm4(uint32_t* r, uint32_t addr) {
    asm volatile("ldmatrix.sync.aligned.m8n8.x4.shared.b16 {%0,%1,%2,%3}, [%4];"
                 : "=r"(r[0]), "=r"(r[1]), "=r"(r[2]), "=r"(r[3]) : "r"(addr));
}
__device__ __forceinline__ void mma16816(float* d, const uint32_t* a, const uint32_t* b) {
    asm volatile("mma.sync.aligned.m16n8k16.row.col.f32.bf16.bf16.f32 "
                 "{%0,%1,%2,%3}, {%4,%5,%6,%7}, {%8,%9}, {%0,%1,%2,%3};"
                 : "+f"(d[0]), "+f"(d[1]), "+f"(d[2]), "+f"(d[3])
                 : "r"(a[0]), "r"(a[1]), "r"(a[2]), "r"(a[3]), "r"(b[0]), "r"(b[1]));
}
// (m1,k1,m2) merge with lowest-index tie-break
__device__ __forceinline__ void tmerge(float& m1, int& k1, float& m2,
                                       float vm1, int vk1, float vm2) {
    if (vm1 < m1 || (vm1 == m1 && vk1 < k1)) {
        m2 = fminf(m1, vm2); m1 = vm1; k1 = vk1;
    } else {
        m2 = fminf(m2, vm1);
    }
}

struct alignas(16) BH8 { __nv_bfloat16 v[8]; };
struct alignas(8)  BH4 { __nv_bfloat16 v[4]; };

// ---------------- k_prep: codebook norms + bf16 round + clears ----------------
__global__ void k_prep(const float* __restrict__ cb) {
    int gt = blockIdx.x * blockDim.x + threadIdx.x;
    int w = gt >> 5, lane = gt & 31;                  // one warp per (t,k) row
    const float4* row = (const float4*)(cb + (size_t)w * D_);
    float4 v = row[lane];
    BH4 h;
    h.v[0] = __float2bfloat16_rn(v.x);
    h.v[1] = __float2bfloat16_rn(v.y);
    h.v[2] = __float2bfloat16_rn(v.z);
    h.v[3] = __float2bfloat16_rn(v.w);
    *(uint2*)(g_cbh + (size_t)w * D_ + lane * 4) = *(uint2*)&h;
    float s = v.x*v.x + v.y*v.y + v.z*v.z + v.w*v.w;
    #pragma unroll
    for (int o = 16; o; o >>= 1) s += __shfl_xor_sync(0xffffffffu, s, o);
    if (lane == 0) { g_cnorm[w] = s; g_used[w] = 0; }
    if (gt == 0) g_amb_count = 0;
}

// ---------------- k_mma: 2-GEMM split (zh+zl)*ch, register-prefetch double buffer ----------------
#define LDB   272
#define OFF_CN   0
#define OFF_AH   2048
#define OFF_AL   (OFF_AH + 128*LDB)     // 36864
#define OFF_B    (OFF_AL + 128*LDB)     // 71680
#define OFF_RM1  (OFF_B  + 128*LDB)     // 106496
#define OFF_RM2  (OFF_RM1 + 128*2*4)
#define OFF_RK1  (OFF_RM2 + 128*2*4)
#define SMEM_MMA (OFF_RK1 + 128*2*4)    // 109568

__global__ void __launch_bounds__(256, 1) k_mma(const float* __restrict__ ze) {
    extern __shared__ char sm[];
    const uint32_t smem_base = smem_to_u32(sm);
    float* cn_s   = (float*)(sm + OFF_CN);
    float* red_m1 = (float*)(sm + OFF_RM1);
    float* red_m2 = (float*)(sm + OFF_RM2);
    int*   red_k1 = (int*)  (sm + OFF_RK1);

    const int tid = threadIdx.x, wid = tid >> 5, l = tid & 31;
    const int wm = wid >> 1, wn = wid & 1;            // 4 x 2 warp grid
    const int bx = blockIdx.x, t = blockIdx.y;

    const char* cb_base = (const char*)(g_cbh + ((size_t)(t * K_)) * D_);
    const int prow = tid >> 4, pseg = tid & 15;       // B-copy mapping: 16 rows / pass

    // prologue: chunk 0 -> registers (overlaps A staging below)
    uint4 pf[8];
    #pragma unroll
    for (int rr = 0; rr < 8; rr++)
        pf[rr] = *(const uint4*)(cb_base + (size_t)(prow + rr * 16) * 256 + pseg * 16);

    // stage codebook norms
    for (int i = tid; i < K_; i += 256) cn_s[i] = g_cnorm[t * K_ + i];

    // A tile: 128 z-rows fp32 -> (zh, zl) bf16 padded rows
    const float* zbase = ze + ((size_t)(bx * 128) * T_ + t) * D_;
    for (int G = tid; G < 2048; G += 256) {
        int m = G >> 4, seg = G & 15;
        const float4* p = (const float4*)(zbase + (size_t)m * (T_ * D_) + seg * 8);
        float4 a = p[0], b = p[1];
        float zf[8] = {a.x, a.y, a.z, a.w, b.x, b.y, b.z, b.w};
        BH8 h, lo;
        #pragma unroll
        for (int i = 0; i < 8; i++) {
            h.v[i]  = __float2bfloat16_rn(zf[i]);
            lo.v[i] = __float2bfloat16_rn(zf[i] - __bfloat162float(h.v[i]));
        }
        *(uint4*)(sm + OFF_AH + m * LDB + seg * 16) = *(uint4*)&h;
        *(uint4*)(sm + OFF_AL + m * LDB + seg * 16) = *(uint4*)&lo;
    }

    // running per-row argmin state (thread tid < 128 owns local row = tid)
    float run_m1 = FINF, run_m2 = FINF; int run_k1 = 0;

    // LDSM base addresses (layout validated R7)
    const uint32_t aAddrH = smem_base + OFF_AH + (wm*32 + (l & 15)) * LDB + ((l >> 4) * 8) * 2;
    const uint32_t aAddrL = aAddrH + (OFF_AL - OFF_AH);
    const int nofs = (l & 7) + ((l >> 4) & 1) * 8;
    const int kofs = ((l >> 3) & 1) * 8;
    const uint32_t bAddr = smem_base + OFF_B + (wn*64 + nofs) * LDB + kofs * 2;

    for (int c = 0; c < 4; c++) {
        // publish prefetched chunk c into the single B buffer
        #pragma unroll
        for (int rr = 0; rr < 8; rr++)
            *(uint4*)(sm + OFF_B + (prow + rr * 16) * LDB + pseg * 16) = pf[rr];
        __syncthreads();   // B visible (and on c=0: A tile + cn_s visible)

        if (c < 3) {       // prefetch chunk c+1; consumed only after next barrier
            const char* src = cb_base + (size_t)(c + 1) * 128 * 256;
            #pragma unroll
            for (int rr = 0; rr < 8; rr++)
                pf[rr] = *(const uint4*)(src + (size_t)(prow + rr * 16) * 256 + pseg * 16);
        }

        float acc[2][8][4];
        #pragma unroll
        for (int mi = 0; mi < 2; mi++)
            #pragma unroll
            for (int ni = 0; ni < 8; ni++)
                #pragma unroll
                for (int j = 0; j < 4; j++) acc[mi][ni][j] = 0.f;

        #pragma unroll 1
        for (int ks = 0; ks < 8; ks++) {
            uint32_t aH[2][4], aL[2][4], bH[4][4];
            ldsm4(aH[0], aAddrH + ks * 32);
            ldsm4(aH[1], aAddrH + 16 * LDB + ks * 32);
            ldsm4(aL[0], aAddrL + ks * 32);
            ldsm4(aL[1], aAddrL + 16 * LDB + ks * 32);
            #pragma unroll
            for (int p = 0; p < 4; p++) ldsm4(bH[p], bAddr + p * 16 * LDB + ks * 32);
            #pragma unroll
            for (int mi = 0; mi < 2; mi++)
                #pragma unroll
                for (int p = 0; p < 4; p++) {
                    mma16816(acc[mi][2*p],   aH[mi], &bH[p][0]);   // zh.ch
                    mma16816(acc[mi][2*p+1], aH[mi], &bH[p][2]);
                    mma16816(acc[mi][2*p],   aL[mi], &bH[p][0]);   // zl.ch
                    mma16816(acc[mi][2*p+1], aL[mi], &bH[p][2]);
                }
        }

        // per-chunk argmin epilogue: v = cn[k] - 2*s
        const int g = l >> 2, q = l & 3;
        #pragma unroll
        for (int mi = 0; mi < 2; mi++) {
            #pragma unroll
            for (int half = 0; half < 2; half++) {
                float m1 = FINF, m2 = FINF; int k1 = 0;
                #pragma unroll
                for (int ni = 0; ni < 8; ni++) {
                    #pragma unroll
                    for (int j = 0; j < 2; j++) {
                        int k = c*128 + wn*64 + ni*8 + 2*q + j;
                        float v = fmaf(-2.f, acc[mi][ni][half*2 + j], cn_s[k]);
                        if (v < m1)      { m2 = m1; m1 = v; k1 = k; }
                        else if (v < m2) { m2 = v; }
                    }
                }
                #pragma unroll
                for (int o = 1; o <= 2; o <<= 1) {    // merge across the 4 lanes of a row
                    float om1 = __shfl_xor_sync(0xffffffffu, m1, o);
                    int   ok1 = __shfl_xor_sync(0xffffffffu, k1, o);
                    float om2 = __shfl_xor_sync(0xffffffffu, m2, o);
                    tmerge(m1, k1, m2, om1, ok1, om2);
                }
                if (q == 0) {
                    int rowl = wm*32 + mi*16 + half*8 + g;
                    red_m1[rowl*2 + wn] = m1;
                    red_m2[rowl*2 + wn] = m2;
                    red_k1[rowl*2 + wn] = k1;
                }
            }
        }
        __syncthreads();   // red ready + all LDSM done (B buffer reusable next iter)
        if (tid < 128) {
            tmerge(run_m1, run_k1, run_m2, red_m1[tid*2+0], red_k1[tid*2+0], red_m2[tid*2+0]);
            tmerge(run_m1, run_k1, run_m2, red_m1[tid*2+1], red_k1[tid*2+1], red_m2[tid*2+1]);
        }
    }

    if (tid < 128) {
        int row = (bx * 128 + tid) * T_ + t;
        g_tokens[row] = run_k1;
        if (run_m2 - run_m1 < EPS) {
            int idx = atomicAdd(&g_amb_count, 1);
            g_amb[idx] = row;
        }
    }
}

// ---------------- k_fix: exact fp32 rescan of ambiguous rows (reference formula, 2-way ILP) ----------------
__global__ void __launch_bounds__(256) k_fix(const float* __restrict__ ze,
                                             const float* __restrict__ cb) {
    __shared__ float zb[8][128];
    const int wid = threadIdx.x >> 5, lane = threadIdx.x & 31;
    const int gw = blockIdx.x * 8 + wid;
    const int nw = gridDim.x * 8;
    const int cnt = g_amb_count;
    for (int i = gw; i < cnt; i += nw) {
        int row = g_amb[i];
        int t = row & (T_ - 1);
        const float4* z4 = (const float4*)(ze + (size_t)row * D_);
        float4 zv = z4[lane];
        ((float4*)zb[wid])[lane] = zv;
        float zn = fmaf(zv.w, zv.w, fmaf(zv.z, zv.z, fmaf(zv.y, zv.y, zv.x * zv.x)));
        #pragma unroll
        for (int o = 16; o; o >>= 1) zn += __shfl_xor_sync(0xffffffffu, zn, o);
        __syncwarp();

        float bv = FINF; int bi = 0;
        for (int j = 0; j < 16; j += 2) {             // two independent FMA chains (ILP)
            int k0 = j * 32 + lane, k1 = k0 + 32;
            const float4* c0 = (const float4*)(cb + ((size_t)(t * K_ + k0)) * D_);
            const float4* c1 = (const float4*)(cb + ((size_t)(t * K_ + k1)) * D_);
            float s0 = 0.f, s1 = 0.f;
            #pragma unroll 8
            for (int d4 = 0; d4 < 32; d4++) {         // strict in-order fp32 chain each
                float4 v0 = c0[d4], v1 = c1[d4];
                float z0 = zb[wid][4*d4 + 0], z1f = zb[wid][4*d4 + 1];
                float z2 = zb[wid][4*d4 + 2], z3f = zb[wid][4*d4 + 3];
                s0 = fmaf(z0, v0.x, s0); s1 = fmaf(z0, v1.x, s1);
                s0 = fmaf(z1f, v0.y, s0); s1 = fmaf(z1f, v1.y, s1);
                s0 = fmaf(z2, v0.z, s0); s1 = fmaf(z2, v1.z, s1);
                s0 = fmaf(z3f, v0.w, s0); s1 = fmaf(z3f, v1.w, s1);
            }
            float v0 = (zn - 2.f * s0) + g_cnorm[t * K_ + k0];   // reference rounding order
            float v1 = (zn - 2.f * s1) + g_cnorm[t * K_ + k1];
            if (v0 < bv) { bv = v0; bi = k0; }        // k0 < k1: scan order preserved
            if (v1 < bv) { bv = v1; bi = k1; }
        }
        #pragma unroll
        for (int o = 16; o; o >>= 1) {                // lowest-index tie-break
            float ov = __shfl_xor_sync(0xffffffffu, bv, o);
            int   oi = __shfl_xor_sync(0xffffffffu, bi, o);
            if (ov < bv || (ov == bv && oi < bi)) { bv = ov; bi = oi; }
        }
        if (lane == 0) g_tokens[row] = bi;
        __syncwarp();
    }
}

// ---------------- k_copy: z_q_st + tokens + used + exact loss partials ----------------
__global__ void k_copy(const float* __restrict__ ze, const float* __restrict__ cb,
                       float* __restrict__ out) {
    __shared__ float ls[8];
    const int wid = threadIdx.x >> 5, lane = threadIdx.x & 31;
    const int row = blockIdx.x * 8 + wid;
    const int t = row & (T_ - 1);
    const int tok = g_tokens[row];
    const float4* cs = (const float4*)(cb + ((size_t)(t * K_ + tok)) * D_);
    const float4* zs = (const float4*)(ze + (size_t)row * D_);
    float4 c = cs[lane], z = zs[lane];
    float4 o;
    o.x = z.x + (c.x - z.x); o.y = z.y + (c.y - z.y);
    o.z = z.z + (c.z - z.z); o.w = z.w + (c.w - z.w);
    ((float4*)(out + (size_t)row * D_))[lane] = o;
    float dx = z.x - c.x, dy = z.y - c.y, dz = z.z - c.z, dw = z.w - c.w;
    float q = fmaf(dw, dw, fmaf(dz, dz, fmaf(dy, dy, dx * dx)));
    #pragma unroll
    for (int of = 16; of; of >>= 1) q += __shfl_xor_sync(0xffffffffu, q, of);
    if (lane == 0) {
        out[NZQ + row] = (float)tok;
        g_used[t * K_ + tok] = 1;
        ls[wid] = q;
    }
    __syncthreads();
    if (threadIdx.x == 0) {
        float s = 0.f;
        #pragma unroll
        for (int i = 0; i < 8; i++) s += ls[i];
        g_partial2[blockIdx.x] = s;
    }
}

// ---------------- k_final: scalars (1024 threads, vectorized) ----------------
__global__ void __launch_bounds__(1024) k_final(float* __restrict__ out) {
    __shared__ double ds[1024];
    __shared__ int    dc[1024];
    const int tid = threadIdx.x;
    double s = 0.0;
    const float4* p4 = (const float4*)g_partial2;     // 16384 floats = 4096 float4
    for (int i = tid; i < 4096; i += 1024) {
        float4 v = p4[i];
        s += (double)((v.x + v.y) + (v.z + v.w));
    }
    int c = 0;
    const uint2* u2 = (const uint2*)g_used;           // 8192 bytes = 1024 uint2
    {
        uint2 v = u2[tid];
        uint32_t m = v.x + v.y;                       // bytes 0/1 -> per-byte sums <=2, no carry
        m = (m & 0x00FF00FFu) + ((m >> 8) & 0x00FF00FFu);
        c = (int)((m & 0xFFFFu) + (m >> 16));
    }
    ds[tid] = s; dc[tid] = c;
    __syncthreads();
    for (int st = 512; st; st >>= 1) {
        if (tid < st) { ds[tid] += ds[tid + st]; dc[tid] += dc[tid + st]; }
        __syncthreads();
    }
    if (tid == 0) {
        out[NZQ + NTOK + 0] = (float)(0.25 * ds[0] / (double)NZQ);
        out[NZQ + NTOK + 1] = (float)dc[0] / (float)(T_ * K_);
    }
}

extern "C" void kernel_launch(void* const* d_in, const int* in_sizes, int n_in,
                              void* d_out, int out_size) {
    const float* ze = (const float*)d_in[0];
    const float* cb = (const float*)d_in[1];
    float* out = (float*)d_out;

    cudaFuncSetAttribute(k_mma, cudaFuncAttributeMaxDynamicSharedMemorySize, SMEM_MMA);

    k_prep<<<1024, 256>>>(cb);
    dim3 gm(B_ / 128, T_);
    k_mma<<<gm, 256, SMEM_MMA>>>(ze);
    k_fix<<<512, 256>>>(ze, cb);
    k_copy<<<NTOK / 8, 256>>>(ze, cb, out);
    k_final<<<1, 1024>>>(out);
}

// round 11
// speedup vs baseline: 1.2639x; 1.0797x over previous
#include <cuda_runtime.h>
#include <cuda_bf16.h>
#include <cstdint>

#define B_   8192
#define T_   16
#define K_   512
#define D_   128
#define NZQ  (B_*T_*D_)      // 16777216
#define NTOK (B_*T_)         // 131072
#define EPS  5e-4f
#define FINF 3.4e38f

// ---------------- device globals (no allocs allowed) ----------------
__device__ __nv_bfloat16 g_cbh[T_*K_*D_];   // 2MB codebook bf16 (hi only)
__device__ float         g_cnorm[T_*K_];
__device__ int           g_tokens[NTOK];
__device__ unsigned char g_used[T_*K_];
__device__ float         g_partial2[NTOK/8];
__device__ int           g_amb[NTOK];
__device__ int           g_amb_count;

// ---------------- PTX helpers (base compute_103 legal) ----------------
__device__ __forceinline__ uint32_t smem_to_u32(const void* p) {
    uint32_t a;
    asm("{ .reg .u64 t; cvta.to.shared.u64 t, %1; cvt.u32.u64 %0, t; }" : "=r"(a) : "l"(p));
    return a;
}
__device__ __forceinline__ void ldsm4(uint32_t* r, uint32_t addr) {
    asm volatile("ldmatrix.sync.aligned.m8n8.x4.shared.b16 {%0,%1,%2,%3}, [%4];"
                 : "=r"(r[0]), "=r"(r[1]), "=r"(r[2]), "=r"(r[3]) : "r"(addr));
}
__device__ __forceinline__ void mma16816(float* d, const uint32_t* a, const uint32_t* b) {
    asm volatile("mma.sync.aligned.m16n8k16.row.col.f32.bf16.bf16.f32 "
                 "{%0,%1,%2,%3}, {%4,%5,%6,%7}, {%8,%9}, {%0,%1,%2,%3};"
                 : "+f"(d[0]), "+f"(d[1]), "+f"(d[2]), "+f"(d[3])
                 : "r"(a[0]), "r"(a[1]), "r"(a[2]), "r"(a[3]), "r"(b[0]), "r"(b[1]));
}
// (m1,k1,m2) merge with lowest-index tie-break
__device__ __forceinline__ void tmerge(float& m1, int& k1, float& m2,
                                       float vm1, int vk1, float vm2) {
    if (vm1 < m1 || (vm1 == m1 && vk1 < k1)) {
        m2 = fminf(m1, vm2); m1 = vm1; k1 = vk1;
    } else {
        m2 = fminf(m2, vm1);
    }
}

struct alignas(16) BH8 { __nv_bfloat16 v[8]; };
struct alignas(8)  BH4 { __nv_bfloat16 v[4]; };

// ---------------- k_prep: codebook norms + bf16 round + clears ----------------
__global__ void k_prep(const float* __restrict__ cb) {
    int gt = blockIdx.x * blockDim.x + threadIdx.x;
    int w = gt >> 5, lane = gt & 31;                  // one warp per (t,k) row
    const float4* row = (const float4*)(cb + (size_t)w * D_);
    float4 v = row[lane];
    BH4 h;
    h.v[0] = __float2bfloat16_rn(v.x);
    h.v[1] = __float2bfloat16_rn(v.y);
    h.v[2] = __float2bfloat16_rn(v.z);
    h.v[3] = __float2bfloat16_rn(v.w);
    *(uint2*)(g_cbh + (size_t)w * D_ + lane * 4) = *(uint2*)&h;
    float s = v.x*v.x + v.y*v.y + v.z*v.z + v.w*v.w;
    #pragma unroll
    for (int o = 16; o; o >>= 1) s += __shfl_xor_sync(0xffffffffu, s, o);
    if (lane == 0) { g_cnorm[w] = s; g_used[w] = 0; }
    if (gt == 0) g_amb_count = 0;
}

// ---------------- k_mma: R7 structure, 2-GEMM split (zh+zl)*ch ----------------
#define LDB   272
#define OFF_CN   0
#define OFF_AH   2048
#define OFF_AL   (OFF_AH + 128*LDB)     // 36864
#define OFF_B    (OFF_AL + 128*LDB)     // 71680
#define OFF_RM1  (OFF_B  + 128*LDB)     // 106496
#define OFF_RM2  (OFF_RM1 + 128*2*4)
#define OFF_RK1  (OFF_RM2 + 128*2*4)
#define SMEM_MMA (OFF_RK1 + 128*2*4)    // 109568

__global__ void __launch_bounds__(256, 1) k_mma(const float* __restrict__ ze) {
    extern __shared__ char sm[];
    const uint32_t smem_base = smem_to_u32(sm);
    float* cn_s   = (float*)(sm + OFF_CN);
    float* red_m1 = (float*)(sm + OFF_RM1);
    float* red_m2 = (float*)(sm + OFF_RM2);
    int*   red_k1 = (int*)  (sm + OFF_RK1);

    const int tid = threadIdx.x, wid = tid >> 5, l = tid & 31;
    const int wm = wid >> 1, wn = wid & 1;            // 4 x 2 warp grid
    const int bx = blockIdx.x, t = blockIdx.y;

    // stage codebook norms
    for (int i = tid; i < K_; i += 256) cn_s[i] = g_cnorm[t * K_ + i];

    // A tile: 128 z-rows fp32 -> (zh, zl) bf16 padded rows
    const float* zbase = ze + ((size_t)(bx * 128) * T_ + t) * D_;
    for (int G = tid; G < 2048; G += 256) {
        int m = G >> 4, seg = G & 15;
        const float4* p = (const float4*)(zbase + (size_t)m * (T_ * D_) + seg * 8);
        float4 a = p[0], b = p[1];
        float zf[8] = {a.x, a.y, a.z, a.w, b.x, b.y, b.z, b.w};
        BH8 h, lo;
        #pragma unroll
        for (int i = 0; i < 8; i++) {
            h.v[i]  = __float2bfloat16_rn(zf[i]);
            lo.v[i] = __float2bfloat16_rn(zf[i] - __bfloat162float(h.v[i]));
        }
        *(uint4*)(sm + OFF_AH + m * LDB + seg * 16) = *(uint4*)&h;
        *(uint4*)(sm + OFF_AL + m * LDB + seg * 16) = *(uint4*)&lo;
    }

    // running per-row argmin state (thread tid < 128 owns local row = tid)
    float run_m1 = FINF, run_m2 = FINF; int run_k1 = 0;

    // LDSM base addresses (layout validated R7)
    const uint32_t aAddrH = smem_base + OFF_AH + (wm*32 + (l & 15)) * LDB + ((l >> 4) * 8) * 2;
    const uint32_t aAddrL = aAddrH + (OFF_AL - OFF_AH);
    const int nofs = (l & 7) + ((l >> 4) & 1) * 8;
    const int kofs = ((l >> 3) & 1) * 8;
    const uint32_t bAddr = smem_base + OFF_B + (wn*64 + nofs) * LDB + kofs * 2;

    const char* cb_base = (const char*)(g_cbh + ((size_t)(t * K_)) * D_);

    for (int c = 0; c < 4; c++) {
        __syncthreads();   // prev chunk's LDSM done -> B reusable (c=0: A/cn visible)
        // load B chunk (128 codes x 128 d bf16 = 32KB), plain LDG->STS (R7-proven)
        {
            const char* src = cb_base + (size_t)c * 128 * 256;
            for (int G = tid; G < 2048; G += 256) {
                int n = G >> 4, seg = G & 15;
                *(uint4*)(sm + OFF_B + n * LDB + seg * 16) =
                    *(const uint4*)(src + (size_t)n * 256 + seg * 16);
            }
        }
        __syncthreads();

        float acc[2][8][4];
        #pragma unroll
        for (int mi = 0; mi < 2; mi++)
            #pragma unroll
            for (int ni = 0; ni < 8; ni++)
                #pragma unroll
                for (int j = 0; j < 4; j++) acc[mi][ni][j] = 0.f;

        #pragma unroll 1
        for (int ks = 0; ks < 8; ks++) {
            uint32_t aH[2][4], aL[2][4], bH[4][4];
            ldsm4(aH[0], aAddrH + ks * 32);
            ldsm4(aH[1], aAddrH + 16 * LDB + ks * 32);
            ldsm4(aL[0], aAddrL + ks * 32);
            ldsm4(aL[1], aAddrL + 16 * LDB + ks * 32);
            #pragma unroll
            for (int p = 0; p < 4; p++) ldsm4(bH[p], bAddr + p * 16 * LDB + ks * 32);
            #pragma unroll
            for (int mi = 0; mi < 2; mi++)
                #pragma unroll
                for (int p = 0; p < 4; p++) {
                    mma16816(acc[mi][2*p],   aH[mi], &bH[p][0]);   // zh.ch
                    mma16816(acc[mi][2*p+1], aH[mi], &bH[p][2]);
                    mma16816(acc[mi][2*p],   aL[mi], &bH[p][0]);   // zl.ch
                    mma16816(acc[mi][2*p+1], aL[mi], &bH[p][2]);
                }
        }

        // per-chunk argmin epilogue: v = cn[k] - 2*s
        const int g = l >> 2, q = l & 3;
        #pragma unroll
        for (int mi = 0; mi < 2; mi++) {
            #pragma unroll
            for (int half = 0; half < 2; half++) {
                float m1 = FINF, m2 = FINF; int k1 = 0;
                #pragma unroll
                for (int ni = 0; ni < 8; ni++) {
                    #pragma unroll
                    for (int j = 0; j < 2; j++) {
                        int k = c*128 + wn*64 + ni*8 + 2*q + j;
                        float v = fmaf(-2.f, acc[mi][ni][half*2 + j], cn_s[k]);
                        if (v < m1)      { m2 = m1; m1 = v; k1 = k; }
                        else if (v < m2) { m2 = v; }
                    }
                }
                #pragma unroll
                for (int o = 1; o <= 2; o <<= 1) {    // merge across the 4 lanes of a row
                    float om1 = __shfl_xor_sync(0xffffffffu, m1, o);
                    int   ok1 = __shfl_xor_sync(0xffffffffu, k1, o);
                    float om2 = __shfl_xor_sync(0xffffffffu, m2, o);
                    tmerge(m1, k1, m2, om1, ok1, om2);
                }
                if (q == 0) {
                    int rowl = wm*32 + mi*16 + half*8 + g;
                    red_m1[rowl*2 + wn] = m1;
                    red_m2[rowl*2 + wn] = m2;
                    red_k1[rowl*2 + wn] = k1;
                }
            }
        }
        __syncthreads();   // red ready + all LDSM of this chunk done
        if (tid < 128) {
            tmerge(run_m1, run_k1, run_m2, red_m1[tid*2+0], red_k1[tid*2+0], red_m2[tid*2+0]);
            tmerge(run_m1, run_k1, run_m2, red_m1[tid*2+1], red_k1[tid*2+1], red_m2[tid*2+1]);
        }
    }

    if (tid < 128) {
        int row = (bx * 128 + tid) * T_ + t;
        g_tokens[row] = run_k1;
        if (run_m2 - run_m1 < EPS) {
            int idx = atomicAdd(&g_amb_count, 1);
            g_amb[idx] = row;
        }
    }
}

// ---------------- k_fix: exact fp32 rescan of ambiguous rows (reference formula, 2-way ILP) ----------------
__global__ void __launch_bounds__(256) k_fix(const float* __restrict__ ze,
                                             const float* __restrict__ cb) {
    __shared__ float zb[8][128];
    const int wid = threadIdx.x >> 5, lane = threadIdx.x & 31;
    const int gw = blockIdx.x * 8 + wid;
    const int nw = gridDim.x * 8;
    const int cnt = g_amb_count;
    for (int i = gw; i < cnt; i += nw) {
        int row = g_amb[i];
        int t = row & (T_ - 1);
        const float4* z4 = (const float4*)(ze + (size_t)row * D_);
        float4 zv = z4[lane];
        ((float4*)zb[wid])[lane] = zv;
        float zn = fmaf(zv.w, zv.w, fmaf(zv.z, zv.z, fmaf(zv.y, zv.y, zv.x * zv.x)));
        #pragma unroll
        for (int o = 16; o; o >>= 1) zn += __shfl_xor_sync(0xffffffffu, zn, o);
        __syncwarp();

        float bv = FINF; int bi = 0;
        for (int j = 0; j < 16; j += 2) {             // two independent FMA chains (ILP)
            int k0 = j * 32 + lane, k1 = k0 + 32;
            const float4* c0 = (const float4*)(cb + ((size_t)(t * K_ + k0)) * D_);
            const float4* c1 = (const float4*)(cb + ((size_t)(t * K_ + k1)) * D_);
            float s0 = 0.f, s1 = 0.f;
            #pragma unroll 8
            for (int d4 = 0; d4 < 32; d4++) {         // strict in-order fp32 chain each
                float4 v0 = c0[d4], v1 = c1[d4];
                float z0 = zb[wid][4*d4 + 0], z1f = zb[wid][4*d4 + 1];
                float z2 = zb[wid][4*d4 + 2], z3f = zb[wid][4*d4 + 3];
                s0 = fmaf(z0, v0.x, s0); s1 = fmaf(z0, v1.x, s1);
                s0 = fmaf(z1f, v0.y, s0); s1 = fmaf(z1f, v1.y, s1);
                s0 = fmaf(z2, v0.z, s0); s1 = fmaf(z2, v1.z, s1);
                s0 = fmaf(z3f, v0.w, s0); s1 = fmaf(z3f, v1.w, s1);
            }
            float v0 = (zn - 2.f * s0) + g_cnorm[t * K_ + k0];   // reference rounding order
            float v1 = (zn - 2.f * s1) + g_cnorm[t * K_ + k1];
            if (v0 < bv) { bv = v0; bi = k0; }        // k0 < k1: scan order preserved
            if (v1 < bv) { bv = v1; bi = k1; }
        }
        #pragma unroll
        for (int o = 16; o; o >>= 1) {                // lowest-index tie-break
            float ov = __shfl_xor_sync(0xffffffffu, bv, o);
            int   oi = __shfl_xor_sync(0xffffffffu, bi, o);
            if (ov < bv || (ov == bv && oi < bi)) { bv = ov; bi = oi; }
        }
        if (lane == 0) g_tokens[row] = bi;
        __syncwarp();
    }
}

// ---------------- k_copy: z_q_st + tokens + used + exact loss partials ----------------
__global__ void k_copy(const float* __restrict__ ze, const float* __restrict__ cb,
                       float* __restrict__ out) {
    __shared__ float ls[8];
    const int wid = threadIdx.x >> 5, lane = threadIdx.x & 31;
    const int row = blockIdx.x * 8 + wid;
    const int t = row & (T_ - 1);
    const int tok = g_tokens[row];
    const float4* cs = (const float4*)(cb + ((size_t)(t * K_ + tok)) * D_);
    const float4* zs = (const float4*)(ze + (size_t)row * D_);
    float4 c = cs[lane], z = zs[lane];
    float4 o;
    o.x = z.x + (c.x - z.x); o.y = z.y + (c.y - z.y);
    o.z = z.z + (c.z - z.z); o.w = z.w + (c.w - z.w);
    ((float4*)(out + (size_t)row * D_))[lane] = o;
    float dx = z.x - c.x, dy = z.y - c.y, dz = z.z - c.z, dw = z.w - c.w;
    float q = fmaf(dw, dw, fmaf(dz, dz, fmaf(dy, dy, dx * dx)));
    #pragma unroll
    for (int of = 16; of; of >>= 1) q += __shfl_xor_sync(0xffffffffu, q, of);
    if (lane == 0) {
        out[NZQ + row] = (float)tok;
        g_used[t * K_ + tok] = 1;
        ls[wid] = q;
    }
    __syncthreads();
    if (threadIdx.x == 0) {
        float s = 0.f;
        #pragma unroll
        for (int i = 0; i < 8; i++) s += ls[i];
        g_partial2[blockIdx.x] = s;
    }
}

// ---------------- k_final: scalars (1024 threads, vectorized) ----------------
__global__ void __launch_bounds__(1024) k_final(float* __restrict__ out) {
    __shared__ double ds[1024];
    __shared__ int    dc[1024];
    const int tid = threadIdx.x;
    double s = 0.0;
    const float4* p4 = (const float4*)g_partial2;     // 16384 floats = 4096 float4
    for (int i = tid; i < 4096; i += 1024) {
        float4 v = p4[i];
        s += (double)((v.x + v.y) + (v.z + v.w));
    }
    int c = 0;
    const uint2* u2 = (const uint2*)g_used;           // 8192 bytes = 1024 uint2
    {
        uint2 v = u2[tid];
        uint32_t m = v.x + v.y;                       // bytes 0/1 -> per-byte sums <=2, no carry
        m = (m & 0x00FF00FFu) + ((m >> 8) & 0x00FF00FFu);
        c = (int)((m & 0xFFFFu) + (m >> 16));
    }
    ds[tid] = s; dc[tid] = c;
    __syncthreads();
    for (int st = 512; st; st >>= 1) {
        if (tid < st) { ds[tid] += ds[tid + st]; dc[tid] += dc[tid + st]; }
        __syncthreads();
    }
    if (tid == 0) {
        out[NZQ + NTOK + 0] = (float)(0.25 * ds[0] / (double)NZQ);
        out[NZQ + NTOK + 1] = (float)dc[0] / (float)(T_ * K_);
    }
}

extern "C" void kernel_launch(void* const* d_in, const int* in_sizes, int n_in,
                              void* d_out, int out_size) {
    const float* ze = (const float*)d_in[0];
    const float* cb = (const float*)d_in[1];
    float* out = (float*)d_out;

    cudaFuncSetAttribute(k_mma, cudaFuncAttributeMaxDynamicSharedMemorySize, SMEM_MMA);

    k_prep<<<1024, 256>>>(cb);
    dim3 gm(B_ / 128, T_);
    k_mma<<<gm, 256, SMEM_MMA>>>(ze);
    k_fix<<<512, 256>>>(ze, cb);
    k_copy<<<NTOK / 8, 256>>>(ze, cb, out);
    k_final<<<1, 1024>>>(out);
}

// round 13
// speedup vs baseline: 2.8301x; 2.2392x over previous
#include <cuda_runtime.h>
#include <cuda_bf16.h>
#include <cstdint>

#define B_   8192
#define T_   16
#define K_   512
#define D_   128
#define NZQ  (B_*T_*D_)      // 16777216
#define NTOK (B_*T_)         // 131072
#define EPS  1e-4f
#define FINF 3.4e38f

// ---------------- device globals (no allocs allowed) ----------------
__device__ __nv_bfloat16 g_cbh[T_*K_*D_];   // 2MB codebook hi split
__device__ __nv_bfloat16 g_cbl[T_*K_*D_];   // 2MB codebook lo split
__device__ float         g_cnorm[T_*K_];
__device__ int           g_tokens[NTOK];
__device__ unsigned char g_used[T_*K_];
__device__ float         g_partial2[NTOK/8];
__device__ int           g_ambt[T_][8192];  // per-t ambiguous row lists
__device__ int           g_acnt[T_];

// ---------------- PTX helpers (base compute_103 legal) ----------------
__device__ __forceinline__ uint32_t smem_to_u32(const void* p) {
    uint32_t a;
    asm("{ .reg .u64 t; cvta.to.shared.u64 t, %1; cvt.u32.u64 %0, t; }" : "=r"(a) : "l"(p));
    return a;
}
__device__ __forceinline__ void ldsm4(uint32_t* r, uint32_t addr) {
    asm volatile("ldmatrix.sync.aligned.m8n8.x4.shared.b16 {%0,%1,%2,%3}, [%4];"
                 : "=r"(r[0]), "=r"(r[1]), "=r"(r[2]), "=r"(r[3]) : "r"(addr));
}
__device__ __forceinline__ void mma16816(float* d, const uint32_t* a, const uint32_t* b) {
    asm volatile("mma.sync.aligned.m16n8k16.row.col.f32.bf16.bf16.f32 "
                 "{%0,%1,%2,%3}, {%4,%5,%6,%7}, {%8,%9}, {%0,%1,%2,%3};"
                 : "+f"(d[0]), "+f"(d[1]), "+f"(d[2]), "+f"(d[3])
                 : "r"(a[0]), "r"(a[1]), "r"(a[2]), "r"(a[3]), "r"(b[0]), "r"(b[1]));
}
// (m1,k1,m2) merge with lowest-index tie-break
__device__ __forceinline__ void tmerge(float& m1, int& k1, float& m2,
                                       float vm1, int vk1, float vm2) {
    if (vm1 < m1 || (vm1 == m1 && vk1 < k1)) {
        m2 = fminf(m1, vm2); m1 = vm1; k1 = vk1;
    } else {
        m2 = fminf(m2, vm1);
    }
}

struct alignas(16) BH8 { __nv_bfloat16 v[8]; };
struct alignas(8)  BH4 { __nv_bfloat16 v[4]; };

// ---------------- k_prep: codebook norms + bf16 hi/lo splits + clears ----------------
__global__ void k_prep(const float* __restrict__ cb) {
    int gt = blockIdx.x * blockDim.x + threadIdx.x;
    int w = gt >> 5, lane = gt & 31;                  // one warp per (t,k) row
    const float4* row = (const float4*)(cb + (size_t)w * D_);
    float4 v = row[lane];
    BH4 h, l;
    float zf[4] = {v.x, v.y, v.z, v.w};
    #pragma unroll
    for (int i = 0; i < 4; i++) {
        h.v[i] = __float2bfloat16_rn(zf[i]);
        l.v[i] = __float2bfloat16_rn(zf[i] - __bfloat162float(h.v[i]));
    }
    *(uint2*)(g_cbh + (size_t)w * D_ + lane * 4) = *(uint2*)&h;
    *(uint2*)(g_cbl + (size_t)w * D_ + lane * 4) = *(uint2*)&l;
    float s = v.x*v.x + v.y*v.y + v.z*v.z + v.w*v.w;
    #pragma unroll
    for (int o = 16; o; o >>= 1) s += __shfl_xor_sync(0xffffffffu, s, o);
    if (lane == 0) { g_cnorm[w] = s; g_used[w] = 0; }
    if (gt < T_) g_acnt[gt] = 0;
}

// ---------------- k_mma: R7 3-GEMM split zh.ch + zh.cl + zl.ch (measured-fastest) ----------------
#define LDB   272
#define OFF_CN   0
#define OFF_AH   2048
#define OFF_AL   (OFF_AH + 128*LDB)     // 36864
#define OFF_BH   (OFF_AL + 128*LDB)     // 71680
#define OFF_BL   (OFF_BH + 128*LDB)     // 106496
#define OFF_RM1  (OFF_BL + 128*LDB)     // 141312
#define OFF_RM2  (OFF_RM1 + 128*2*4)
#define OFF_RK1  (OFF_RM2 + 128*2*4)
#define SMEM_MMA (OFF_RK1 + 128*2*4)    // 144384

__global__ void __launch_bounds__(256, 1) k_mma(const float* __restrict__ ze) {
    extern __shared__ char sm[];
    const uint32_t smem_base = smem_to_u32(sm);
    float* cn_s   = (float*)(sm + OFF_CN);
    float* red_m1 = (float*)(sm + OFF_RM1);
    float* red_m2 = (float*)(sm + OFF_RM2);
    int*   red_k1 = (int*)  (sm + OFF_RK1);

    const int tid = threadIdx.x, wid = tid >> 5, l = tid & 31;
    const int wm = wid >> 1, wn = wid & 1;            // 4 x 2 warp grid
    const int bx = blockIdx.x, t = blockIdx.y;

    // stage codebook norms
    for (int i = tid; i < K_; i += 256) cn_s[i] = g_cnorm[t * K_ + i];

    // A tile: 128 z-rows fp32 -> (zh, zl) bf16 padded rows
    const float* zbase = ze + ((size_t)(bx * 128) * T_ + t) * D_;
    for (int G = tid; G < 2048; G += 256) {
        int m = G >> 4, seg = G & 15;
        const float4* p = (const float4*)(zbase + (size_t)m * (T_ * D_) + seg * 8);
        float4 a = p[0], b = p[1];
        float zf[8] = {a.x, a.y, a.z, a.w, b.x, b.y, b.z, b.w};
        BH8 h, lo;
        #pragma unroll
        for (int i = 0; i < 8; i++) {
            h.v[i]  = __float2bfloat16_rn(zf[i]);
            lo.v[i] = __float2bfloat16_rn(zf[i] - __bfloat162float(h.v[i]));
        }
        *(uint4*)(sm + OFF_AH + m * LDB + seg * 16) = *(uint4*)&h;
        *(uint4*)(sm + OFF_AL + m * LDB + seg * 16) = *(uint4*)&lo;
    }

    // running per-row argmin state (thread tid < 128 owns local row = tid)
    float run_m1 = FINF, run_m2 = FINF; int run_k1 = 0;

    // LDSM base addresses (layout validated R7)
    const uint32_t aAddrH = smem_base + OFF_AH + (wm*32 + (l & 15)) * LDB + ((l >> 4) * 8) * 2;
    const uint32_t aAddrL = aAddrH + (OFF_AL - OFF_AH);
    const int nofs = (l & 7) + ((l >> 4) & 1) * 8;
    const int kofs = ((l >> 3) & 1) * 8;
    const uint32_t bAddrH = smem_base + OFF_BH + (wn*64 + nofs) * LDB + kofs * 2;
    const uint32_t bAddrL = bAddrH + (OFF_BL - OFF_BH);

    for (int c = 0; c < 4; c++) {
        __syncthreads();   // prev chunk's LDSM done -> B reusable (c=0: A/cn visible)
        // load B chunk (128 codes x 128 d, hi+lo) into padded smem rows
        {
            const char* sh = (const char*)(g_cbh + ((size_t)(t * K_ + c * 128)) * D_);
            const char* sl = (const char*)(g_cbl + ((size_t)(t * K_ + c * 128)) * D_);
            for (int G = tid; G < 2048; G += 256) {
                int n = G >> 4, seg = G & 15;
                *(uint4*)(sm + OFF_BH + n * LDB + seg * 16) = *(const uint4*)(sh + (size_t)n * 256 + seg * 16);
                *(uint4*)(sm + OFF_BL + n * LDB + seg * 16) = *(const uint4*)(sl + (size_t)n * 256 + seg * 16);
            }
        }
        __syncthreads();

        float acc[2][8][4];
        #pragma unroll
        for (int mi = 0; mi < 2; mi++)
            #pragma unroll
            for (int ni = 0; ni < 8; ni++)
                #pragma unroll
                for (int j = 0; j < 4; j++) acc[mi][ni][j] = 0.f;

        #pragma unroll 1
        for (int ks = 0; ks < 8; ks++) {
            uint32_t aH[2][4], aL[2][4], bH[4][4], bL[4][4];
            ldsm4(aH[0], aAddrH + ks * 32);
            ldsm4(aH[1], aAddrH + 16 * LDB + ks * 32);
            ldsm4(aL[0], aAddrL + ks * 32);
            ldsm4(aL[1], aAddrL + 16 * LDB + ks * 32);
            #pragma unroll
            for (int p = 0; p < 4; p++) {
                ldsm4(bH[p], bAddrH + p * 16 * LDB + ks * 32);
                ldsm4(bL[p], bAddrL + p * 16 * LDB + ks * 32);
            }
            #pragma unroll
            for (int mi = 0; mi < 2; mi++)
                #pragma unroll
                for (int p = 0; p < 4; p++) {
                    mma16816(acc[mi][2*p],   aH[mi], &bH[p][0]);   // zh.ch
                    mma16816(acc[mi][2*p+1], aH[mi], &bH[p][2]);
                    mma16816(acc[mi][2*p],   aH[mi], &bL[p][0]);   // zh.cl
                    mma16816(acc[mi][2*p+1], aH[mi], &bL[p][2]);
                    mma16816(acc[mi][2*p],   aL[mi], &bH[p][0]);   // zl.ch
                    mma16816(acc[mi][2*p+1], aL[mi], &bH[p][2]);
                }
        }

        // per-chunk argmin epilogue: v = cn[k] - 2*s
        const int g = l >> 2, q = l & 3;
        #pragma unroll
        for (int mi = 0; mi < 2; mi++) {
            #pragma unroll
            for (int half = 0; half < 2; half++) {
                float m1 = FINF, m2 = FINF; int k1 = 0;
                #pragma unroll
                for (int ni = 0; ni < 8; ni++) {
                    #pragma unroll
                    for (int j = 0; j < 2; j++) {
                        int k = c*128 + wn*64 + ni*8 + 2*q + j;
                        float v = fmaf(-2.f, acc[mi][ni][half*2 + j], cn_s[k]);
                        if (v < m1)      { m2 = m1; m1 = v; k1 = k; }
                        else if (v < m2) { m2 = v; }
                    }
                }
                #pragma unroll
                for (int o = 1; o <= 2; o <<= 1) {    // merge across the 4 lanes of a row
                    float om1 = __shfl_xor_sync(0xffffffffu, m1, o);
                    int   ok1 = __shfl_xor_sync(0xffffffffu, k1, o);
                    float om2 = __shfl_xor_sync(0xffffffffu, m2, o);
                    tmerge(m1, k1, m2, om1, ok1, om2);
                }
                if (q == 0) {
                    int rowl = wm*32 + mi*16 + half*8 + g;
                    red_m1[rowl*2 + wn] = m1;
                    red_m2[rowl*2 + wn] = m2;
                    red_k1[rowl*2 + wn] = k1;
                }
            }
        }
        __syncthreads();   // red ready + all LDSM of this chunk done
        if (tid < 128) {
            tmerge(run_m1, run_k1, run_m2, red_m1[tid*2+0], red_k1[tid*2+0], red_m2[tid*2+0]);
            tmerge(run_m1, run_k1, run_m2, red_m1[tid*2+1], red_k1[tid*2+1], red_m2[tid*2+1]);
        }
    }

    if (tid < 128) {
        int row = (bx * 128 + tid) * T_ + t;
        g_tokens[row] = run_k1;
        if (run_m2 - run_m1 < EPS) {
            int idx = atomicAdd(&g_acnt[t], 1);
            if (idx < 8192) g_ambt[t][idx] = row;
        }
    }
}

// ---------------- k_fix2: batched exact fp32 rescan, codebook staged in smem ----------------
// grid (8, T_): CTA (cx, t) handles rows gw=cx*8+wid stride 64 of list t.
#define FIXLDS 132
#define FIX_SMEM ((128*FIXLDS + 8*128 + 8*128 + 8*128) * 4)   // cbT + zrow + bvs + bis = 79872B

__global__ void __launch_bounds__(256) k_fix2(const float* __restrict__ ze,
                                              const float* __restrict__ cb) {
    extern __shared__ float fsm[];
    float* cbT  = fsm;                      // [128 d][FIXLDS] transposed chunk
    float* zrow = fsm + 128*FIXLDS;         // [8][128]
    float* bvs  = zrow + 8*128;             // [8][128] running best val
    int*   bis  = (int*)(bvs + 8*128);      // [8][128] running best idx

    const int t = blockIdx.y, cx = blockIdx.x;
    const int tid = threadIdx.x, wid = tid >> 5, lane = tid & 31;
    const int gw = cx * 8 + wid;            // 0..63
    int cnt = g_acnt[t]; if (cnt > 8192) cnt = 8192;
    if (cnt == 0) return;

    for (int j = tid; j < 8*128; j += 256) { bvs[j] = FINF; bis[j] = 0; }

    for (int ch = 0; ch < 4; ch++) {
        __syncthreads();
        // load + transpose codebook chunk (fp32): cbT[d][r] = cb[t, ch*128+r, d]
        {
            const float* src = cb + ((size_t)(t * K_ + ch * 128)) * D_;
            int d4 = 4 * wid + (lane >> 3);     // 0..31 -> d base 4*d4
            int r0 = lane & 7;
            for (int r = r0; r < 128; r += 8) {
                float4 v = *(const float4*)(src + (size_t)r * D_ + 4 * d4);
                cbT[(4*d4 + 0) * FIXLDS + r] = v.x;
                cbT[(4*d4 + 1) * FIXLDS + r] = v.y;
                cbT[(4*d4 + 2) * FIXLDS + r] = v.z;
                cbT[(4*d4 + 3) * FIXLDS + r] = v.w;
            }
        }
        __syncthreads();

        for (int j = 0; gw + j*64 < cnt; j++) {
            int row = g_ambt[t][gw + j*64];
            // stage z row (fp32) + exact zn (R7-validated shuffle fold)
            const float4* z4 = (const float4*)(ze + (size_t)row * D_);
            float4 zv = z4[lane];
            *(float4*)(zrow + wid*128 + lane*4) = zv;
            float zn = fmaf(zv.w, zv.w, fmaf(zv.z, zv.z, fmaf(zv.y, zv.y, zv.x * zv.x)));
            #pragma unroll
            for (int o = 16; o; o >>= 1) zn += __shfl_xor_sync(0xffffffffu, zn, o);
            __syncwarp();

            // lane owns codes k = ch*128 + lane*4 + {0,1,2,3}: 4 strict in-order fp32 chains
            float s0 = 0.f, s1 = 0.f, s2 = 0.f, s3 = 0.f;
            const float* zp = zrow + wid*128;
            #pragma unroll 8
            for (int d = 0; d < 128; d++) {
                float z = zp[d];
                float4 cv = *(const float4*)(cbT + d * FIXLDS + lane * 4);
                s0 = fmaf(z, cv.x, s0); s1 = fmaf(z, cv.y, s1);
                s2 = fmaf(z, cv.z, s2); s3 = fmaf(z, cv.w, s3);
            }
            const int kb = ch*128 + lane*4;
            float v0 = (zn - 2.f * s0) + g_cnorm[t*K_ + kb + 0];  // reference rounding order
            float v1 = (zn - 2.f * s1) + g_cnorm[t*K_ + kb + 1];
            float v2 = (zn - 2.f * s2) + g_cnorm[t*K_ + kb + 2];
            float v3 = (zn - 2.f * s3) + g_cnorm[t*K_ + kb + 3];
            float bv = v0; int bi = kb;
            if (v1 < bv) { bv = v1; bi = kb + 1; }
            if (v2 < bv) { bv = v2; bi = kb + 2; }
            if (v3 < bv) { bv = v3; bi = kb + 3; }
            #pragma unroll
            for (int o = 16; o; o >>= 1) {      // lowest-index tie-break
                float ov = __shfl_xor_sync(0xffffffffu, bv, o);
                int   oi = __shfl_xor_sync(0xffffffffu, bi, o);
                if (ov < bv || (ov == bv && oi < bi)) { bv = ov; bi = oi; }
            }
            if (lane == 0) {
                float cur = bvs[wid*128 + j];
                int  curi = bis[wid*128 + j];
                if (bv < cur || (bv == cur && bi < curi)) {
                    bvs[wid*128 + j] = bv; bis[wid*128 + j] = bi;
                }
            }
            __syncwarp();   // zrow reuse safe
        }
    }

    for (int j = 0; gw + j*64 < cnt; j++)
        if (lane == 0) g_tokens[g_ambt[t][gw + j*64]] = bis[wid*128 + j];
}

// ---------------- k_copy: z_q_st + tokens + used + exact loss partials ----------------
__global__ void k_copy(const float* __restrict__ ze, const float* __restrict__ cb,
                       float* __restrict__ out) {
    __shared__ float ls[8];
    const int wid = threadIdx.x >> 5, lane = threadIdx.x & 31;
    const int row = blockIdx.x * 8 + wid;
    const int t = row & (T_ - 1);
    const int tok = g_tokens[row];
    const float4* cs = (const float4*)(cb + ((size_t)(t * K_ + tok)) * D_);
    const float4* zs = (const float4*)(ze + (size_t)row * D_);
    float4 c = cs[lane], z = zs[lane];
    float4 o;
    o.x = z.x + (c.x - z.x); o.y = z.y + (c.y - z.y);
    o.z = z.z + (c.z - z.z); o.w = z.w + (c.w - z.w);
    ((float4*)(out + (size_t)row * D_))[lane] = o;
    float dx = z.x - c.x, dy = z.y - c.y, dz = z.z - c.z, dw = z.w - c.w;
    float q = fmaf(dw, dw, fmaf(dz, dz, fmaf(dy, dy, dx * dx)));
    #pragma unroll
    for (int of = 16; of; of >>= 1) q += __shfl_xor_sync(0xffffffffu, q, of);
    if (lane == 0) {
        out[NZQ + row] = (float)tok;
        g_used[t * K_ + tok] = 1;
        ls[wid] = q;
    }
    __syncthreads();
    if (threadIdx.x == 0) {
        float s = 0.f;
        #pragma unroll
        for (int i = 0; i < 8; i++) s += ls[i];
        g_partial2[blockIdx.x] = s;
    }
}

// ---------------- k_final: scalars (1024 threads, vectorized) ----------------
__global__ void __launch_bounds__(1024) k_final(float* __restrict__ out) {
    __shared__ double ds[1024];
    __shared__ int    dc[1024];
    const int tid = threadIdx.x;
    double s = 0.0;
    const float4* p4 = (const float4*)g_partial2;     // 16384 floats = 4096 float4
    for (int i = tid; i < 4096; i += 1024) {
        float4 v = p4[i];
        s += (double)((v.x + v.y) + (v.z + v.w));
    }
    int c = 0;
    const uint2* u2 = (const uint2*)g_used;           // 8192 bytes = 1024 uint2
    {
        uint2 v = u2[tid];
        uint32_t m = v.x + v.y;                       // bytes 0/1 -> per-byte sums <=2, no carry
        m = (m & 0x00FF00FFu) + ((m >> 8) & 0x00FF00FFu);
        c = (int)((m & 0xFFFFu) + (m >> 16));
    }
    ds[tid] = s; dc[tid] = c;
    __syncthreads();
    for (int st = 512; st; st >>= 1) {
        if (tid < st) { ds[tid] += ds[tid + st]; dc[tid] += dc[tid + st]; }
        __syncthreads();
    }
    if (tid == 0) {
        out[NZQ + NTOK + 0] = (float)(0.25 * ds[0] / (double)NZQ);
        out[NZQ + NTOK + 1] = (float)dc[0] / (float)(T_ * K_);
    }
}

extern "C" void kernel_launch(void* const* d_in, const int* in_sizes, int n_in,
                              void* d_out, int out_size) {
    const float* ze = (const float*)d_in[0];
    const float* cb = (const float*)d_in[1];
    float* out = (float*)d_out;

    cudaFuncSetAttribute(k_mma, cudaFuncAttributeMaxDynamicSharedMemorySize, SMEM_MMA);
    cudaFuncSetAttribute(k_fix2, cudaFuncAttributeMaxDynamicSharedMemorySize, FIX_SMEM);

    k_prep<<<1024, 256>>>(cb);
    dim3 gm(B_ / 128, T_);
    k_mma<<<gm, 256, SMEM_MMA>>>(ze);
    dim3 gf(8, T_);
    k_fix2<<<gf, 256, FIX_SMEM>>>(ze, cb);
    k_copy<<<NTOK / 8, 256>>>(ze, cb, out);
    k_final<<<1, 1024>>>(out);
}

// round 16
// speedup vs baseline: 3.1342x; 1.1075x over previous
#include <cuda_runtime.h>
#include <cuda_bf16.h>
#include <cstdint>

#define B_   8192
#define T_   16
#define K_   512
#define D_   128
#define NZQ  (B_*T_*D_)      // 16777216
#define NTOK (B_*T_)         // 131072
#define EPS  5e-4f
#define FINF 3.4e38f

// ---------------- device globals (no allocs allowed) ----------------
__device__ __nv_bfloat16 g_cbh[T_*K_*D_];   // 2MB codebook bf16 (hi)
__device__ float         g_cnorm[T_*K_];
__device__ int           g_tokens[NTOK];
__device__ unsigned char g_used[T_*K_];
__device__ float         g_partial2[NTOK/8];
__device__ int           g_ambt[T_][8192];  // per-t ambiguous row lists
__device__ int           g_acnt[T_];

// ---------------- PTX helpers (base compute_103 legal) ----------------
__device__ __forceinline__ uint32_t smem_to_u32(const void* p) {
    uint32_t a;
    asm("{ .reg .u64 t; cvta.to.shared.u64 t, %1; cvt.u32.u64 %0, t; }" : "=r"(a) : "l"(p));
    return a;
}
__device__ __forceinline__ void ldsm4(uint32_t* r, uint32_t addr) {
    asm volatile("ldmatrix.sync.aligned.m8n8.x4.shared.b16 {%0,%1,%2,%3}, [%4];"
                 : "=r"(r[0]), "=r"(r[1]), "=r"(r[2]), "=r"(r[3]) : "r"(addr));
}
__device__ __forceinline__ void mma16816(float* d, const uint32_t* a, const uint32_t* b) {
    asm volatile("mma.sync.aligned.m16n8k16.row.col.f32.bf16.bf16.f32 "
                 "{%0,%1,%2,%3}, {%4,%5,%6,%7}, {%8,%9}, {%0,%1,%2,%3};"
                 : "+f"(d[0]), "+f"(d[1]), "+f"(d[2]), "+f"(d[3])
                 : "r"(a[0]), "r"(a[1]), "r"(a[2]), "r"(a[3]), "r"(b[0]), "r"(b[1]));
}
// (m1,k1,m2) merge with lowest-index tie-break
__device__ __forceinline__ void tmerge(float& m1, int& k1, float& m2,
                                       float vm1, int vk1, float vm2) {
    if (vm1 < m1 || (vm1 == m1 && vk1 < k1)) {
        m2 = fminf(m1, vm2); m1 = vm1; k1 = vk1;
    } else {
        m2 = fminf(m2, vm1);
    }
}

struct alignas(16) BH8 { __nv_bfloat16 v[8]; };
struct alignas(8)  BH4 { __nv_bfloat16 v[4]; };

// ---------------- k_prep: codebook norms + bf16 round + clears ----------------
__global__ void k_prep(const float* __restrict__ cb) {
    int gt = blockIdx.x * blockDim.x + threadIdx.x;
    int w = gt >> 5, lane = gt & 31;                  // one warp per (t,k) row
    const float4* row = (const float4*)(cb + (size_t)w * D_);
    float4 v = row[lane];
    BH4 h;
    h.v[0] = __float2bfloat16_rn(v.x);
    h.v[1] = __float2bfloat16_rn(v.y);
    h.v[2] = __float2bfloat16_rn(v.z);
    h.v[3] = __float2bfloat16_rn(v.w);
    *(uint2*)(g_cbh + (size_t)w * D_ + lane * 4) = *(uint2*)&h;
    float s = v.x*v.x + v.y*v.y + v.z*v.z + v.w*v.w;
    #pragma unroll
    for (int o = 16; o; o >>= 1) s += __shfl_xor_sync(0xffffffffu, s, o);
    if (lane == 0) { g_cnorm[w] = s; g_used[w] = 0; }
    if (gt < T_) g_acnt[gt] = 0;
}

// ---------------- k_mma: 2-GEMM split (zh+zl).ch, R7-proven load structure ----------------
#define LDB   272
#define OFF_CN   0
#define OFF_AH   2048
#define OFF_AL   (OFF_AH + 128*LDB)     // 36864
#define OFF_BH   (OFF_AL + 128*LDB)     // 71680
#define OFF_RM1  (OFF_BH + 128*LDB)     // 106496
#define OFF_RM2  (OFF_RM1 + 128*2*4)
#define OFF_RK1  (OFF_RM2 + 128*2*4)
#define SMEM_MMA (OFF_RK1 + 128*2*4)    // 109568

__global__ void __launch_bounds__(256, 1) k_mma(const float* __restrict__ ze) {
    extern __shared__ char sm[];
    const uint32_t smem_base = smem_to_u32(sm);
    float* cn_s   = (float*)(sm + OFF_CN);
    float* red_m1 = (float*)(sm + OFF_RM1);
    float* red_m2 = (float*)(sm + OFF_RM2);
    int*   red_k1 = (int*)  (sm + OFF_RK1);

    const int tid = threadIdx.x, wid = tid >> 5, l = tid & 31;
    const int wm = wid >> 1, wn = wid & 1;            // 4 x 2 warp grid
    const int bx = blockIdx.x, t = blockIdx.y;

    // stage codebook norms
    for (int i = tid; i < K_; i += 256) cn_s[i] = g_cnorm[t * K_ + i];

    // A tile: 128 z-rows fp32 -> (zh, zl) bf16 padded rows
    const float* zbase = ze + ((size_t)(bx * 128) * T_ + t) * D_;
    for (int G = tid; G < 2048; G += 256) {
        int m = G >> 4, seg = G & 15;
        const float4* p = (const float4*)(zbase + (size_t)m * (T_ * D_) + seg * 8);
        float4 a = p[0], b = p[1];
        float zf[8] = {a.x, a.y, a.z, a.w, b.x, b.y, b.z, b.w};
        BH8 h, lo;
        #pragma unroll
        for (int i = 0; i < 8; i++) {
            h.v[i]  = __float2bfloat16_rn(zf[i]);
            lo.v[i] = __float2bfloat16_rn(zf[i] - __bfloat162float(h.v[i]));
        }
        *(uint4*)(sm + OFF_AH + m * LDB + seg * 16) = *(uint4*)&h;
        *(uint4*)(sm + OFF_AL + m * LDB + seg * 16) = *(uint4*)&lo;
    }

    // running per-row argmin state (thread tid < 128 owns local row = tid)
    float run_m1 = FINF, run_m2 = FINF; int run_k1 = 0;

    // LDSM base addresses (layout validated R7)
    const uint32_t aAddrH = smem_base + OFF_AH + (wm*32 + (l & 15)) * LDB + ((l >> 4) * 8) * 2;
    const uint32_t aAddrL = aAddrH + (OFF_AL - OFF_AH);
    const int nofs = (l & 7) + ((l >> 4) & 1) * 8;
    const int kofs = ((l >> 3) & 1) * 8;
    const uint32_t bAddrH = smem_base + OFF_BH + (wn*64 + nofs) * LDB + kofs * 2;

    const char* cb_base = (const char*)(g_cbh + ((size_t)(t * K_)) * D_);

    for (int c = 0; c < 4; c++) {
        __syncthreads();   // prev chunk's LDSM done -> B reusable (c=0: A/cn visible)
        // load B chunk (128 codes x 128 d bf16 hi = 32KB), plain LDG->STS (R7-proven)
        {
            const char* src = cb_base + (size_t)c * 128 * 256;
            for (int G = tid; G < 2048; G += 256) {
                int n = G >> 4, seg = G & 15;
                *(uint4*)(sm + OFF_BH + n * LDB + seg * 16) =
                    *(const uint4*)(src + (size_t)n * 256 + seg * 16);
            }
        }
        __syncthreads();

        float acc[2][8][4];
        #pragma unroll
        for (int mi = 0; mi < 2; mi++)
            #pragma unroll
            for (int ni = 0; ni < 8; ni++)
                #pragma unroll
                for (int j = 0; j < 4; j++) acc[mi][ni][j] = 0.f;

        #pragma unroll 1
        for (int ks = 0; ks < 8; ks++) {
            uint32_t aH[2][4], aL[2][4], bH[4][4];
            ldsm4(aH[0], aAddrH + ks * 32);
            ldsm4(aH[1], aAddrH + 16 * LDB + ks * 32);
            ldsm4(aL[0], aAddrL + ks * 32);
            ldsm4(aL[1], aAddrL + 16 * LDB + ks * 32);
            #pragma unroll
            for (int p = 0; p < 4; p++) ldsm4(bH[p], bAddrH + p * 16 * LDB + ks * 32);
            #pragma unroll
            for (int mi = 0; mi < 2; mi++)
                #pragma unroll
                for (int p = 0; p < 4; p++) {
                    mma16816(acc[mi][2*p],   aH[mi], &bH[p][0]);   // zh.ch
                    mma16816(acc[mi][2*p+1], aH[mi], &bH[p][2]);
                    mma16816(acc[mi][2*p],   aL[mi], &bH[p][0]);   // zl.ch
                    mma16816(acc[mi][2*p+1], aL[mi], &bH[p][2]);
                }
        }

        // per-chunk argmin epilogue: v = cn[k] - 2*s
        const int g = l >> 2, q = l & 3;
        #pragma unroll
        for (int mi = 0; mi < 2; mi++) {
            #pragma unroll
            for (int half = 0; half < 2; half++) {
                float m1 = FINF, m2 = FINF; int k1 = 0;
                #pragma unroll
                for (int ni = 0; ni < 8; ni++) {
                    #pragma unroll
                    for (int j = 0; j < 2; j++) {
                        int k = c*128 + wn*64 + ni*8 + 2*q + j;
                        float v = fmaf(-2.f, acc[mi][ni][half*2 + j], cn_s[k]);
                        if (v < m1)      { m2 = m1; m1 = v; k1 = k; }
                        else if (v < m2) { m2 = v; }
                    }
                }
                #pragma unroll
                for (int o = 1; o <= 2; o <<= 1) {    // merge across the 4 lanes of a row
                    float om1 = __shfl_xor_sync(0xffffffffu, m1, o);
                    int   ok1 = __shfl_xor_sync(0xffffffffu, k1, o);
                    float om2 = __shfl_xor_sync(0xffffffffu, m2, o);
                    tmerge(m1, k1, m2, om1, ok1, om2);
                }
                if (q == 0) {
                    int rowl = wm*32 + mi*16 + half*8 + g;
                    red_m1[rowl*2 + wn] = m1;
                    red_m2[rowl*2 + wn] = m2;
                    red_k1[rowl*2 + wn] = k1;
                }
            }
        }
        __syncthreads();   // red ready + all LDSM of this chunk done
        if (tid < 128) {
            tmerge(run_m1, run_k1, run_m2, red_m1[tid*2+0], red_k1[tid*2+0], red_m2[tid*2+0]);
            tmerge(run_m1, run_k1, run_m2, red_m1[tid*2+1], red_k1[tid*2+1], red_m2[tid*2+1]);
        }
    }

    if (tid < 128) {
        int row = (bx * 128 + tid) * T_ + t;
        g_tokens[row] = run_k1;
        if (run_m2 - run_m1 < EPS) {
            int idx = atomicAdd(&g_acnt[t], 1);
            if (idx < 8192) g_ambt[t][idx] = row;
        }
    }
}

// ---------------- k_fix2: batched exact fp32 rescan, codebook staged in smem ----------------
// grid (16, T_): CTA (cx, t) handles rows gw=cx*8+wid stride 128 of list t.
#define FIXLDS 132
#define FIX_SMEM ((128*FIXLDS + 8*128 + 8*128 + 8*128) * 4)   // cbT + zrow + bvs + bis = 79872B

__global__ void __launch_bounds__(256) k_fix2(const float* __restrict__ ze,
                                              const float* __restrict__ cb) {
    extern __shared__ float fsm[];
    float* cbT  = fsm;                      // [128 d][FIXLDS] transposed chunk
    float* zrow = fsm + 128*FIXLDS;         // [8][128]
    float* bvs  = zrow + 8*128;             // [8][128] running best val
    int*   bis  = (int*)(bvs + 8*128);      // [8][128] running best idx

    const int t = blockIdx.y, cx = blockIdx.x;
    const int tid = threadIdx.x, wid = tid >> 5, lane = tid & 31;
    const int gw = cx * 8 + wid;            // 0..127
    int cnt = g_acnt[t]; if (cnt > 8192) cnt = 8192;
    if (cnt == 0) return;

    for (int j = tid; j < 8*128; j += 256) { bvs[j] = FINF; bis[j] = 0; }

    for (int ch = 0; ch < 4; ch++) {
        __syncthreads();
        // load + transpose codebook chunk (fp32): cbT[d][r] = cb[t, ch*128+r, d]
        {
            const float* src = cb + ((size_t)(t * K_ + ch * 128)) * D_;
            int d4 = 4 * wid + (lane >> 3);     // 0..31 -> d base 4*d4
            int r0 = lane & 7;
            for (int r = r0; r < 128; r += 8) {
                float4 v = *(const float4*)(src + (size_t)r * D_ + 4 * d4);
                cbT[(4*d4 + 0) * FIXLDS + r] = v.x;
                cbT[(4*d4 + 1) * FIXLDS + r] = v.y;
                cbT[(4*d4 + 2) * FIXLDS + r] = v.z;
                cbT[(4*d4 + 3) * FIXLDS + r] = v.w;
            }
        }
        __syncthreads();

        for (int j = 0; gw + j*128 < cnt; j++) {
            int row = g_ambt[t][gw + j*128];
            // stage z row (fp32) + exact zn (R7-validated shuffle fold)
            const float4* z4 = (const float4*)(ze + (size_t)row * D_);
            float4 zv = z4[lane];
            *(float4*)(zrow + wid*128 + lane*4) = zv;
            float zn = fmaf(zv.w, zv.w, fmaf(zv.z, zv.z, fmaf(zv.y, zv.y, zv.x * zv.x)));
            #pragma unroll
            for (int o = 16; o; o >>= 1) zn += __shfl_xor_sync(0xffffffffu, zn, o);
            __syncwarp();

            // lane owns codes k = ch*128 + lane*4 + {0,1,2,3}: 4 strict in-order fp32 chains
            float s0 = 0.f, s1 = 0.f, s2 = 0.f, s3 = 0.f;
            const float* zp = zrow + wid*128;
            #pragma unroll 8
            for (int d = 0; d < 128; d++) {
                float z = zp[d];
                float4 cv = *(const float4*)(cbT + d * FIXLDS + lane * 4);
                s0 = fmaf(z, cv.x, s0); s1 = fmaf(z, cv.y, s1);
                s2 = fmaf(z, cv.z, s2); s3 = fmaf(z, cv.w, s3);
            }
            const int kb = ch*128 + lane*4;
            float v0 = (zn - 2.f * s0) + g_cnorm[t*K_ + kb + 0];  // reference rounding order
            float v1 = (zn - 2.f * s1) + g_cnorm[t*K_ + kb + 1];
            float v2 = (zn - 2.f * s2) + g_cnorm[t*K_ + kb + 2];
            float v3 = (zn - 2.f * s3) + g_cnorm[t*K_ + kb + 3];
            float bv = v0; int bi = kb;
            if (v1 < bv) { bv = v1; bi = kb + 1; }
            if (v2 < bv) { bv = v2; bi = kb + 2; }
            if (v3 < bv) { bv = v3; bi = kb + 3; }
            #pragma unroll
            for (int o = 16; o; o >>= 1) {      // lowest-index tie-break
                float ov = __shfl_xor_sync(0xffffffffu, bv, o);
                int   oi = __shfl_xor_sync(0xffffffffu, bi, o);
                if (ov < bv || (ov == bv && oi < bi)) { bv = ov; bi = oi; }
            }
            if (lane == 0) {
                float cur = bvs[wid*128 + j];
                int  curi = bis[wid*128 + j];
                if (bv < cur || (bv == cur && bi < curi)) {
                    bvs[wid*128 + j] = bv; bis[wid*128 + j] = bi;
                }
            }
            __syncwarp();   // zrow reuse safe
        }
    }

    for (int j = 0; gw + j*128 < cnt; j++)
        if (lane == 0) g_tokens[g_ambt[t][gw + j*128]] = bis[wid*128 + j];
}

// ---------------- k_copy: z_q_st + tokens + used + exact loss partials ----------------
__global__ void k_copy(const float* __restrict__ ze, const float* __restrict__ cb,
                       float* __restrict__ out) {
    __shared__ float ls[8];
    const int wid = threadIdx.x >> 5, lane = threadIdx.x & 31;
    const int row = blockIdx.x * 8 + wid;
    const int t = row & (T_ - 1);
    const int tok = g_tokens[row];
    const float4* cs = (const float4*)(cb + ((size_t)(t * K_ + tok)) * D_);
    const float4* zs = (const float4*)(ze + (size_t)row * D_);
    float4 c = cs[lane], z = zs[lane];
    float4 o;
    o.x = z.x + (c.x - z.x); o.y = z.y + (c.y - z.y);
    o.z = z.z + (c.z - z.z); o.w = z.w + (c.w - z.w);
    ((float4*)(out + (size_t)row * D_))[lane] = o;
    float dx = z.x - c.x, dy = z.y - c.y, dz = z.z - c.z, dw = z.w - c.w;
    float q = fmaf(dw, dw, fmaf(dz, dz, fmaf(dy, dy, dx * dx)));
    #pragma unroll
    for (int of = 16; of; of >>= 1) q += __shfl_xor_sync(0xffffffffu, q, of);
    if (lane == 0) {
        out[NZQ + row] = (float)tok;
        g_used[t * K_ + tok] = 1;
        ls[wid] = q;
    }
    __syncthreads();
    if (threadIdx.x == 0) {
        float s = 0.f;
        #pragma unroll
        for (int i = 0; i < 8; i++) s += ls[i];
        g_partial2[blockIdx.x] = s;
    }
}

// ---------------- k_final: scalars (1024 threads, vectorized) ----------------
__global__ void __launch_bounds__(1024) k_final(float* __restrict__ out) {
    __shared__ double ds[1024];
    __shared__ int    dc[1024];
    const int tid = threadIdx.x;
    double s = 0.0;
    const float4* p4 = (const float4*)g_partial2;     // 16384 floats = 4096 float4
    for (int i = tid; i < 4096; i += 1024) {
        float4 v = p4[i];
        s += (double)((v.x + v.y) + (v.z + v.w));
    }
    int c = 0;
    const uint2* u2 = (const uint2*)g_used;           // 8192 bytes = 1024 uint2
    {
        uint2 v = u2[tid];
        uint32_t m = v.x + v.y;                       // bytes 0/1 -> per-byte sums <=2, no carry
        m = (m & 0x00FF00FFu) + ((m >> 8) & 0x00FF00FFu);
        c = (int)((m & 0xFFFFu) + (m >> 16));
    }
    ds[tid] = s; dc[tid] = c;
    __syncthreads();
    for (int st = 512; st; st >>= 1) {
        if (tid < st) { ds[tid] += ds[tid + st]; dc[tid] += dc[tid + st]; }
        __syncthreads();
    }
    if (tid == 0) {
        out[NZQ + NTOK + 0] = (float)(0.25 * ds[0] / (double)NZQ);
        out[NZQ + NTOK + 1] = (float)dc[0] / (float)(T_ * K_);
    }
}

extern "C" void kernel_launch(void* const* d_in, const int* in_sizes, int n_in,
                              void* d_out, int out_size) {
    const float* ze = (const float*)d_in[0];
    const float* cb = (const float*)d_in[1];
    float* out = (float*)d_out;

    cudaFuncSetAttribute(k_mma, cudaFuncAttributeMaxDynamicSharedMemorySize, SMEM_MMA);
    cudaFuncSetAttribute(k_fix2, cudaFuncAttributeMaxDynamicSharedMemorySize, FIX_SMEM);

    k_prep<<<1024, 256>>>(cb);
    dim3 gm(B_ / 128, T_);
    k_mma<<<gm, 256, SMEM_MMA>>>(ze);
    dim3 gf(16, T_);
    k_fix2<<<gf, 256, FIX_SMEM>>>(ze, cb);
    k_copy<<<NTOK / 8, 256>>>(ze, cb, out);
    k_final<<<1, 1024>>>(out);
}